// round 7
// baseline (speedup 1.0000x reference)
#include <cuda_runtime.h>
#include <cuda_bf16.h>
#include <stdint.h>

#define TH 512
#define TM 64
#define HID 512
#define NIN 16
#define NOUT 136
#define HS 520              // H row stride (bf16): conflict-free for ldmatrix
#define NETS 137

#define XS_OFF  0
#define HH_OFF  4096
#define HL_OFF  (HH_OFF + 66560)        // 64*520*2
#define NET_OFF (HL_OFF + 66560)
#define SMEM_BYTES (NET_OFF + 35072)    // 172288

// fragment-ordered weights: [ks][ng][lane] -> {bhi0, bhi1, blo0, blo1}
__device__ __align__(16) uint4 g_W1f[32 * 64 * 32];   // 1 MB
__device__ __align__(16) uint4 g_W2f[32 * 20 * 32];   // 320 KB (N padded to 160)

__device__ __forceinline__ uint32_t pack_bf2(float a, float b)
{
    __nv_bfloat162 p = __floats2bfloat162_rn(a, b);
    return *(uint32_t*)&p;
}

__device__ __forceinline__ uint4 make_frag(float v00, float v01, float v10, float v11)
{
    float h00 = __bfloat162float(__float2bfloat16(v00));
    float h01 = __bfloat162float(__float2bfloat16(v01));
    float h10 = __bfloat162float(__float2bfloat16(v10));
    float h11 = __bfloat162float(__float2bfloat16(v11));
    uint4 o;
    o.x = pack_bf2(h00, h01);
    o.y = pack_bf2(h10, h11);
    o.z = pack_bf2(v00 - h00, v01 - h01);
    o.w = pack_bf2(v10 - h10, v11 - h11);
    return o;
}

__global__ void prep_weights(const float* __restrict__ W1,
                             const float* __restrict__ W2)
{
    int idx = blockIdx.x * blockDim.x + threadIdx.x;
    const int T1 = 32 * 64 * 32;
    const int T2 = 32 * 20 * 32;
    if (idx < T1) {
        int lane = idx & 31, ng = (idx >> 5) & 63, ks = idx >> 11;
        int g = lane >> 2, t = lane & 3;
        int n = ng * 8 + g;
        int k0 = ks * 16 + 2 * t;
        g_W1f[idx] = make_frag(W1[(k0    )*HID + n], W1[(k0 + 1)*HID + n],
                               W1[(k0 + 8)*HID + n], W1[(k0 + 9)*HID + n]);
    } else if (idx < T1 + T2) {
        int j = idx - T1;
        int lane = j & 31, ng = (j >> 5) % 20, ks = j / (20 * 32);
        int g = lane >> 2, t = lane & 3;
        int n = ng * 8 + g;
        int k0 = ks * 16 + 2 * t;
        float v00 = (n < NOUT) ? W2[(k0    )*NOUT + n] : 0.0f;
        float v01 = (n < NOUT) ? W2[(k0 + 1)*NOUT + n] : 0.0f;
        float v10 = (n < NOUT) ? W2[(k0 + 8)*NOUT + n] : 0.0f;
        float v11 = (n < NOUT) ? W2[(k0 + 9)*NOUT + n] : 0.0f;
        g_W2f[j] = make_frag(v00, v01, v10, v11);
    }
}

__device__ __forceinline__ void mma16816(float* d, const uint32_t* a,
                                         uint32_t b0, uint32_t b1)
{
    asm volatile(
        "mma.sync.aligned.m16n8k16.row.col.f32.bf16.bf16.f32 "
        "{%0,%1,%2,%3}, {%4,%5,%6,%7}, {%8,%9}, {%0,%1,%2,%3};\n"
        : "+f"(d[0]), "+f"(d[1]), "+f"(d[2]), "+f"(d[3])
        : "r"(a[0]), "r"(a[1]), "r"(a[2]), "r"(a[3]),
          "r"(b0), "r"(b1));
}

__device__ __forceinline__ void ldsm4(uint32_t* r, uint32_t saddr)
{
    asm volatile("ldmatrix.sync.aligned.m8n8.x4.shared.b16 {%0,%1,%2,%3}, [%4];\n"
                 : "=r"(r[0]), "=r"(r[1]), "=r"(r[2]), "=r"(r[3])
                 : "r"(saddr));
}

__device__ __forceinline__ float ftanh(float x)
{
    float xc = fminf(fmaxf(x, -15.0f), 15.0f);
    float e  = __expf(2.0f * xc);
    return __fdividef(e - 1.0f, e + 1.0f);
}

__device__ __forceinline__ void split_store2(__nv_bfloat16* Hh, __nv_bfloat16* Hl,
                                             int idx, float v0, float v1)
{
    __nv_bfloat162 hp = __floats2bfloat162_rn(v0, v1);
    float r0 = v0 - __bfloat162float(hp.x);
    float r1 = v1 - __bfloat162float(hp.y);
    __nv_bfloat162 lp = __floats2bfloat162_rn(r0, r1);
    *(__nv_bfloat162*)(Hh + idx) = hp;
    *(__nv_bfloat162*)(Hl + idx) = lp;
}

__global__ __launch_bounds__(TH, 1)
void ptpd_mma_kernel(const float* __restrict__ pts,
                     const float* __restrict__ W0, const float* __restrict__ b0,
                     const float* __restrict__ b1, const float* __restrict__ b2,
                     float* __restrict__ out)
{
    extern __shared__ char sm[];
    float*          Xs  = (float*)(sm + XS_OFF);
    __nv_bfloat16*  Hh  = (__nv_bfloat16*)(sm + HH_OFF);
    __nv_bfloat16*  Hl  = (__nv_bfloat16*)(sm + HL_OFF);
    float*          netS = (float*)(sm + NET_OFF);

    const uint32_t smb = (uint32_t)__cvta_generic_to_shared(sm);
    const uint32_t hhS = smb + HH_OFF;
    const uint32_t hlS = smb + HL_OFF;

    const int tid  = threadIdx.x;
    const int lane = tid & 31;
    const int wid  = tid >> 5;      // 0..15
    const int g    = lane >> 2;
    const int t    = lane & 3;
    const long row0 = (long)blockIdx.x * TM;

    const int arow  = lane & 15;
    const int acol8 = (lane >> 4) << 3;

    // ---------------- X tile ----------------
    for (int i = tid; i < TM*NIN; i += TH)
        Xs[i] = pts[row0*NIN + i];
    __syncthreads();

    // ---------------- layer 0 (scalar; each thread 1 col, 64 rows) ----------------
    {
        const int c0 = tid;
        float w0a[NIN];
        #pragma unroll
        for (int k = 0; k < NIN; k++) w0a[k] = W0[k*HID + c0];
        const float ba = b0[c0];
        for (int r = 0; r < TM; r++) {
            float a = ba;
            #pragma unroll
            for (int k = 0; k < NIN; k++)
                a = fmaf(Xs[r*NIN + k], w0a[k], a);
            a = ftanh(a);
            __nv_bfloat16 ah = __float2bfloat16(a);
            Hh[r*HS + c0] = ah;
            Hl[r*HS + c0] = __float2bfloat16(a - __bfloat162float(ah));
        }
    }
    __syncthreads();

    // =============== layer 1: 16 warps, each owns 32 n-cols, all 64 rows ===============
    {
        float acc1[4][4][4];    // [m-tile][n-tile][frag]
        #pragma unroll
        for (int nt = 0; nt < 4; nt++) {
            int col = wid*32 + nt*8 + 2*t;
            float bv0 = b1[col], bv1 = b1[col + 1];
            #pragma unroll
            for (int mt = 0; mt < 4; mt++) {
                acc1[mt][nt][0] = bv0; acc1[mt][nt][1] = bv1;
                acc1[mt][nt][2] = bv0; acc1[mt][nt][3] = bv1;
            }
        }

        for (int ks = 0; ks < 32; ks++) {
            uint4 bv[4];
            #pragma unroll
            for (int nt = 0; nt < 4; nt++)
                bv[nt] = g_W1f[(ks*64 + wid*4 + nt)*32 + lane];

            uint32_t af[4][4];
            // hi terms: ah*bh + ah*bl
            #pragma unroll
            for (int mt = 0; mt < 4; mt++) {
                int ro = (mt*16 + arow)*HS + ks*16 + acol8;
                ldsm4(af[mt], hhS + ro*2);
            }
            #pragma unroll
            for (int nt = 0; nt < 4; nt++)
                #pragma unroll
                for (int mt = 0; mt < 4; mt++) {
                    mma16816(acc1[mt][nt], af[mt], bv[nt].x, bv[nt].y);
                    mma16816(acc1[mt][nt], af[mt], bv[nt].z, bv[nt].w);
                }
            // lo term: al*bh
            #pragma unroll
            for (int mt = 0; mt < 4; mt++) {
                int ro = (mt*16 + arow)*HS + ks*16 + acol8;
                ldsm4(af[mt], hlS + ro*2);
            }
            #pragma unroll
            for (int nt = 0; nt < 4; nt++)
                #pragma unroll
                for (int mt = 0; mt < 4; mt++)
                    mma16816(acc1[mt][nt], af[mt], bv[nt].x, bv[nt].y);
        }

        __syncthreads();    // all warps done READING H0 before overwrite

        // tanh + split -> H1 (overwrites H0 buffers)
        #pragma unroll
        for (int mt = 0; mt < 4; mt++)
            #pragma unroll
            for (int nt = 0; nt < 4; nt++) {
                int r   = mt*16 + g;
                int col = wid*32 + nt*8 + 2*t;
                split_store2(Hh, Hl, r*HS + col,
                             ftanh(acc1[mt][nt][0]), ftanh(acc1[mt][nt][1]));
                split_store2(Hh, Hl, (r + 8)*HS + col,
                             ftanh(acc1[mt][nt][2]), ftanh(acc1[mt][nt][3]));
            }
    }
    __syncthreads();

    // =============== layer 2: 4 m-warps x 4 n-warps (N padded 160) ===============
    {
        const int wm = wid & 3;     // 16 rows each
        const int wn = wid >> 2;    // 40 cols each (5 n-tiles)
        float acc2[5][4];
        #pragma unroll
        for (int nt = 0; nt < 5; nt++) {
            int col = wn*40 + nt*8 + 2*t;
            float bv0 = (col     < NOUT) ? b2[col]     : 0.0f;
            float bv1 = (col + 1 < NOUT) ? b2[col + 1] : 0.0f;
            acc2[nt][0] = bv0; acc2[nt][1] = bv1;
            acc2[nt][2] = bv0; acc2[nt][3] = bv1;
        }

        for (int ks = 0; ks < 32; ks++) {
            uint4 bv[5];
            #pragma unroll
            for (int nt = 0; nt < 5; nt++)
                bv[nt] = g_W2f[(ks*20 + wn*5 + nt)*32 + lane];

            uint32_t ah[4], al[4];
            int ro = (wm*16 + arow)*HS + ks*16 + acol8;
            ldsm4(ah, hhS + ro*2);
            ldsm4(al, hlS + ro*2);

            #pragma unroll
            for (int nt = 0; nt < 5; nt++) {
                mma16816(acc2[nt], ah, bv[nt].x, bv[nt].y);
                mma16816(acc2[nt], ah, bv[nt].z, bv[nt].w);
                mma16816(acc2[nt], al, bv[nt].x, bv[nt].y);
            }
        }

        // net -> smem
        #pragma unroll
        for (int nt = 0; nt < 5; nt++) {
            int r   = wm*16 + g;
            int col = wn*40 + nt*8 + 2*t;
            if (col + 1 < NOUT) {
                netS[r*NETS + col]           = acc2[nt][0];
                netS[r*NETS + col + 1]       = acc2[nt][1];
                netS[(r + 8)*NETS + col]     = acc2[nt][2];
                netS[(r + 8)*NETS + col + 1] = acc2[nt][3];
            }
        }
    }
    __syncthreads();

    // ---------------- quadratic form ----------------
    if (tid < TM) {
        const float* nn = netS + tid*NETS;
        const float* xv = Xs + tid*NIN;
        float x[NIN], sx = 0.0f;
        #pragma unroll
        for (int i = 0; i < NIN; i++) { x[i] = xv[i]; sx = fmaf(x[i], x[i], sx); }
        float y[NIN];
        #pragma unroll
        for (int j = 0; j < NIN; j++) y[j] = 0.0f;
        int tt = 0;
        #pragma unroll
        for (int i = 0; i < NIN; i++) {
            #pragma unroll
            for (int j = 0; j <= i; j++) {
                y[j] = fmaf(nn[tt], x[i], y[j]);
                tt++;
            }
        }
        float v = 0.0f;
        #pragma unroll
        for (int j = 0; j < NIN; j++) v = fmaf(y[j], y[j], v);
        out[row0 + tid] = v + 1e-6f * sx;
    }
}

extern "C" void kernel_launch(void* const* d_in, const int* in_sizes, int n_in,
                              void* d_out, int out_size)
{
    const float* pts = (const float*)d_in[0];
    const float* W0  = (const float*)d_in[1];
    const float* b0  = (const float*)d_in[2];
    const float* W1  = (const float*)d_in[3];
    const float* b1  = (const float*)d_in[4];
    const float* W2  = (const float*)d_in[5];
    const float* b2  = (const float*)d_in[6];
    float* out = (float*)d_out;

    const int B = in_sizes[0] / NIN;

    cudaFuncSetAttribute(ptpd_mma_kernel,
                         cudaFuncAttributeMaxDynamicSharedMemorySize, SMEM_BYTES);

    const int prep_threads = 32*64*32 + 32*20*32;
    prep_weights<<<(prep_threads + 255)/256, 256>>>(W1, W2);

    ptpd_mma_kernel<<<B/TM, TH, SMEM_BYTES>>>(pts, W0, b0, b1, b2, out);
}

// round 8
// speedup vs baseline: 1.0626x; 1.0626x over previous
#include <cuda_runtime.h>
#include <cuda_bf16.h>
#include <stdint.h>

#define TH 256
#define TM 64
#define HID 512
#define NIN 16
#define NOUT 136
#define HS 520              // H row stride (bf16): conflict-free for ldmatrix
#define NETS 137

#define XS_OFF  0
#define HH_OFF  4096
#define HL_OFF  (HH_OFF + 66560)        // 64*520*2
#define NET_OFF (HL_OFF + 66560)
#define SMEM_BYTES (NET_OFF + 35072)    // 172288

// fragment-ordered weights: [ks][ng][lane] -> {bhi0, bhi1, blo0, blo1}
__device__ __align__(16) uint4 g_W1f[32 * 64 * 32];   // 1 MB
__device__ __align__(16) uint4 g_W2f[32 * 20 * 32];   // 320 KB (N padded to 160)

__device__ __forceinline__ uint32_t pack_bf2(float a, float b)
{
    __nv_bfloat162 p = __floats2bfloat162_rn(a, b);
    return *(uint32_t*)&p;
}

__device__ __forceinline__ uint4 make_frag(float v00, float v01, float v10, float v11)
{
    float h00 = __bfloat162float(__float2bfloat16(v00));
    float h01 = __bfloat162float(__float2bfloat16(v01));
    float h10 = __bfloat162float(__float2bfloat16(v10));
    float h11 = __bfloat162float(__float2bfloat16(v11));
    uint4 o;
    o.x = pack_bf2(h00, h01);
    o.y = pack_bf2(h10, h11);
    o.z = pack_bf2(v00 - h00, v01 - h01);
    o.w = pack_bf2(v10 - h10, v11 - h11);
    return o;
}

__global__ void prep_weights(const float* __restrict__ W1,
                             const float* __restrict__ W2)
{
    int idx = blockIdx.x * blockDim.x + threadIdx.x;
    const int T1 = 32 * 64 * 32;
    const int T2 = 32 * 20 * 32;
    if (idx < T1) {
        int lane = idx & 31, ng = (idx >> 5) & 63, ks = idx >> 11;
        int g = lane >> 2, t = lane & 3;
        int n = ng * 8 + g;
        int k0 = ks * 16 + 2 * t;
        g_W1f[idx] = make_frag(W1[(k0    )*HID + n], W1[(k0 + 1)*HID + n],
                               W1[(k0 + 8)*HID + n], W1[(k0 + 9)*HID + n]);
    } else if (idx < T1 + T2) {
        int j = idx - T1;
        int lane = j & 31, ng = (j >> 5) % 20, ks = j / (20 * 32);
        int g = lane >> 2, t = lane & 3;
        int n = ng * 8 + g;
        int k0 = ks * 16 + 2 * t;
        float v00 = (n < NOUT) ? W2[(k0    )*NOUT + n] : 0.0f;
        float v01 = (n < NOUT) ? W2[(k0 + 1)*NOUT + n] : 0.0f;
        float v10 = (n < NOUT) ? W2[(k0 + 8)*NOUT + n] : 0.0f;
        float v11 = (n < NOUT) ? W2[(k0 + 9)*NOUT + n] : 0.0f;
        g_W2f[j] = make_frag(v00, v01, v10, v11);
    }
}

__device__ __forceinline__ void mma16816(float* d, const uint32_t* a,
                                         uint32_t b0, uint32_t b1)
{
    asm volatile(
        "mma.sync.aligned.m16n8k16.row.col.f32.bf16.bf16.f32 "
        "{%0,%1,%2,%3}, {%4,%5,%6,%7}, {%8,%9}, {%0,%1,%2,%3};\n"
        : "+f"(d[0]), "+f"(d[1]), "+f"(d[2]), "+f"(d[3])
        : "r"(a[0]), "r"(a[1]), "r"(a[2]), "r"(a[3]),
          "r"(b0), "r"(b1));
}

__device__ __forceinline__ void ldsm4(uint32_t* r, uint32_t saddr)
{
    asm volatile("ldmatrix.sync.aligned.m8n8.x4.shared.b16 {%0,%1,%2,%3}, [%4];\n"
                 : "=r"(r[0]), "=r"(r[1]), "=r"(r[2]), "=r"(r[3])
                 : "r"(saddr));
}

__device__ __forceinline__ float ftanh(float x)
{
    float xc = fminf(fmaxf(x, -15.0f), 15.0f);
    float e  = __expf(2.0f * xc);
    return __fdividef(e - 1.0f, e + 1.0f);
}

__device__ __forceinline__ void split_store2(__nv_bfloat16* Hh, __nv_bfloat16* Hl,
                                             int idx, float v0, float v1)
{
    __nv_bfloat162 hp = __floats2bfloat162_rn(v0, v1);
    float r0 = v0 - __bfloat162float(hp.x);
    float r1 = v1 - __bfloat162float(hp.y);
    __nv_bfloat162 lp = __floats2bfloat162_rn(r0, r1);
    *(__nv_bfloat162*)(Hh + idx) = hp;
    *(__nv_bfloat162*)(Hl + idx) = lp;
}

__global__ __launch_bounds__(TH, 1)
void ptpd_mma_kernel(const float* __restrict__ pts,
                     const float* __restrict__ W0, const float* __restrict__ b0,
                     const float* __restrict__ b1, const float* __restrict__ b2,
                     float* __restrict__ out)
{
    extern __shared__ char sm[];
    float*          Xs  = (float*)(sm + XS_OFF);
    __nv_bfloat16*  Hh  = (__nv_bfloat16*)(sm + HH_OFF);
    __nv_bfloat16*  Hl  = (__nv_bfloat16*)(sm + HL_OFF);
    float*          netS = (float*)(sm + NET_OFF);

    const uint32_t smb = (uint32_t)__cvta_generic_to_shared(sm);
    const uint32_t hhS = smb + HH_OFF;
    const uint32_t hlS = smb + HL_OFF;

    const int tid  = threadIdx.x;
    const int lane = tid & 31;
    const int wid  = tid >> 5;
    const int g    = lane >> 2;
    const int t    = lane & 3;
    const long row0 = (long)blockIdx.x * TM;

    const int arow  = lane & 15;
    const int acol8 = (lane >> 4) << 3;

    // ---------------- X tile ----------------
    for (int i = tid; i < TM*NIN; i += TH)
        Xs[i] = pts[row0*NIN + i];
    __syncthreads();

    // ---------------- layer 0 (scalar) ----------------
    {
        const int c0 = tid, c1 = tid + 256;
        float w0a[NIN], w0b[NIN];
        #pragma unroll
        for (int k = 0; k < NIN; k++) {
            w0a[k] = W0[k*HID + c0];
            w0b[k] = W0[k*HID + c1];
        }
        const float ba = b0[c0], bb = b0[c1];
        for (int r = 0; r < TM; r++) {
            float a = ba, b = bb;
            #pragma unroll
            for (int k = 0; k < NIN; k++) {
                const float x = Xs[r*NIN + k];
                a = fmaf(x, w0a[k], a);
                b = fmaf(x, w0b[k], b);
            }
            a = ftanh(a); b = ftanh(b);
            __nv_bfloat16 ah = __float2bfloat16(a);
            Hh[r*HS + c0] = ah;
            Hl[r*HS + c0] = __float2bfloat16(a - __bfloat162float(ah));
            __nv_bfloat16 bh = __float2bfloat16(b);
            Hh[r*HS + c1] = bh;
            Hl[r*HS + c1] = __float2bfloat16(b - __bfloat162float(bh));
        }
    }
    __syncthreads();

    // =============== layer 1: each warp owns 64 n-cols, all 64 rows ===============
    // TERM-MAJOR MMA ordering: each accumulator revisited every 32 MMAs.
    {
        float acc1[4][8][4];
        #pragma unroll
        for (int nt = 0; nt < 8; nt++) {
            int col = wid*64 + nt*8 + 2*t;
            float bv0 = b1[col], bv1 = b1[col + 1];
            #pragma unroll
            for (int mt = 0; mt < 4; mt++) {
                acc1[mt][nt][0] = bv0; acc1[mt][nt][1] = bv1;
                acc1[mt][nt][2] = bv0; acc1[mt][nt][3] = bv1;
            }
        }

        for (int ks = 0; ks < 32; ks++) {
            // all 8 B fragments (independent LDG.128s, issued up front)
            uint4 bv[8];
            #pragma unroll
            for (int nt = 0; nt < 8; nt++)
                bv[nt] = g_W1f[(ks*64 + wid*8 + nt)*32 + lane];

            // A fragments hi+lo
            uint32_t ah[4][4], al[4][4];
            #pragma unroll
            for (int mt = 0; mt < 4; mt++) {
                int ro = (mt*16 + arow)*HS + ks*16 + acol8;
                ldsm4(ah[mt], hhS + ro*2);
                ldsm4(al[mt], hlS + ro*2);
            }

            // term 0: ah * bh
            #pragma unroll
            for (int nt = 0; nt < 8; nt++)
                #pragma unroll
                for (int mt = 0; mt < 4; mt++)
                    mma16816(acc1[mt][nt], ah[mt], bv[nt].x, bv[nt].y);
            // term 1: ah * bl
            #pragma unroll
            for (int nt = 0; nt < 8; nt++)
                #pragma unroll
                for (int mt = 0; mt < 4; mt++)
                    mma16816(acc1[mt][nt], ah[mt], bv[nt].z, bv[nt].w);
            // term 2: al * bh
            #pragma unroll
            for (int nt = 0; nt < 8; nt++)
                #pragma unroll
                for (int mt = 0; mt < 4; mt++)
                    mma16816(acc1[mt][nt], al[mt], bv[nt].x, bv[nt].y);
        }

        __syncthreads();    // all warps done READING H0 before overwrite

        // tanh + split -> H1 (overwrites H0 buffers)
        #pragma unroll
        for (int mt = 0; mt < 4; mt++)
            #pragma unroll
            for (int nt = 0; nt < 8; nt++) {
                int r   = mt*16 + g;
                int col = wid*64 + nt*8 + 2*t;
                split_store2(Hh, Hl, r*HS + col,
                             ftanh(acc1[mt][nt][0]), ftanh(acc1[mt][nt][1]));
                split_store2(Hh, Hl, (r + 8)*HS + col,
                             ftanh(acc1[mt][nt][2]), ftanh(acc1[mt][nt][3]));
            }
    }
    __syncthreads();

    // =============== layer 2: 2 m-warps x 4 n-warps (N padded 160) ===============
    {
        const int wm = wid & 1;
        const int wn = wid >> 1;
        float acc2[2][5][4];
        #pragma unroll
        for (int nt = 0; nt < 5; nt++) {
            int col = wn*40 + nt*8 + 2*t;
            float bv0 = (col     < NOUT) ? b2[col]     : 0.0f;
            float bv1 = (col + 1 < NOUT) ? b2[col + 1] : 0.0f;
            #pragma unroll
            for (int mt = 0; mt < 2; mt++) {
                acc2[mt][nt][0] = bv0; acc2[mt][nt][1] = bv1;
                acc2[mt][nt][2] = bv0; acc2[mt][nt][3] = bv1;
            }
        }

        for (int ks = 0; ks < 32; ks++) {
            uint4 bv[5];
            #pragma unroll
            for (int nt = 0; nt < 5; nt++)
                bv[nt] = g_W2f[(ks*20 + wn*5 + nt)*32 + lane];

            uint32_t ah[2][4], al[2][4];
            #pragma unroll
            for (int mt = 0; mt < 2; mt++) {
                int ro = (wm*32 + mt*16 + arow)*HS + ks*16 + acol8;
                ldsm4(ah[mt], hhS + ro*2);
                ldsm4(al[mt], hlS + ro*2);
            }

            // term-major
            #pragma unroll
            for (int nt = 0; nt < 5; nt++)
                #pragma unroll
                for (int mt = 0; mt < 2; mt++)
                    mma16816(acc2[mt][nt], ah[mt], bv[nt].x, bv[nt].y);
            #pragma unroll
            for (int nt = 0; nt < 5; nt++)
                #pragma unroll
                for (int mt = 0; mt < 2; mt++)
                    mma16816(acc2[mt][nt], ah[mt], bv[nt].z, bv[nt].w);
            #pragma unroll
            for (int nt = 0; nt < 5; nt++)
                #pragma unroll
                for (int mt = 0; mt < 2; mt++)
                    mma16816(acc2[mt][nt], al[mt], bv[nt].x, bv[nt].y);
        }

        // net -> smem
        #pragma unroll
        for (int mt = 0; mt < 2; mt++)
            #pragma unroll
            for (int nt = 0; nt < 5; nt++) {
                int r   = wm*32 + mt*16 + g;
                int col = wn*40 + nt*8 + 2*t;
                if (col + 1 < NOUT) {
                    netS[r*NETS + col]           = acc2[mt][nt][0];
                    netS[r*NETS + col + 1]       = acc2[mt][nt][1];
                    netS[(r + 8)*NETS + col]     = acc2[mt][nt][2];
                    netS[(r + 8)*NETS + col + 1] = acc2[mt][nt][3];
                }
            }
    }
    __syncthreads();

    // ---------------- quadratic form ----------------
    if (tid < TM) {
        const float* nn = netS + tid*NETS;
        const float* xv = Xs + tid*NIN;
        float x[NIN], sx = 0.0f;
        #pragma unroll
        for (int i = 0; i < NIN; i++) { x[i] = xv[i]; sx = fmaf(x[i], x[i], sx); }
        float y[NIN];
        #pragma unroll
        for (int j = 0; j < NIN; j++) y[j] = 0.0f;
        int tt = 0;
        #pragma unroll
        for (int i = 0; i < NIN; i++) {
            #pragma unroll
            for (int j = 0; j <= i; j++) {
                y[j] = fmaf(nn[tt], x[i], y[j]);
                tt++;
            }
        }
        float v = 0.0f;
        #pragma unroll
        for (int j = 0; j < NIN; j++) v = fmaf(y[j], y[j], v);
        out[row0 + tid] = v + 1e-6f * sx;
    }
}

extern "C" void kernel_launch(void* const* d_in, const int* in_sizes, int n_in,
                              void* d_out, int out_size)
{
    const float* pts = (const float*)d_in[0];
    const float* W0  = (const float*)d_in[1];
    const float* b0  = (const float*)d_in[2];
    const float* W1  = (const float*)d_in[3];
    const float* b1  = (const float*)d_in[4];
    const float* W2  = (const float*)d_in[5];
    const float* b2  = (const float*)d_in[6];
    float* out = (float*)d_out;

    const int B = in_sizes[0] / NIN;

    cudaFuncSetAttribute(ptpd_mma_kernel,
                         cudaFuncAttributeMaxDynamicSharedMemorySize, SMEM_BYTES);

    const int prep_threads = 32*64*32 + 32*20*32;
    prep_weights<<<(prep_threads + 255)/256, 256>>>(W1, W2);

    ptpd_mma_kernel<<<B/TM, TH, SMEM_BYTES>>>(pts, W0, b0, b1, b2, out);
}